// round 16
// baseline (speedup 1.0000x reference)
#include <cuda_runtime.h>
#include <cstdint>

#define NN 512
#define LUT_N 83521            // 17^4
#define NPIX (4 * NN * NN)

// ---------------- device scratch ----------------
__device__ int8_t g_q0[3 * LUT_N];        // stage-0 quantized LUT (int8)
__device__ uint4  g_q1lo[3 * LUT_N];      // stage-1 LUT ch0-7  as bf16 pairs (16B/row)
__device__ uint4  g_q1hi[3 * LUT_N];      // stage-1 LUT ch8-15 as bf16 pairs (16B/row)
__device__ float  g_x1[NPIX];             // stage-0 output image (integers 0..255)

// staging for constant uploads (written by setup_weights, memcpy'd to __constant__)
__device__ unsigned long long g_stg_w0[108];
__device__ unsigned long long g_stg_w1[108];
__device__ unsigned long long g_stg_b0[12];
__device__ unsigned long long g_stg_b1[12];
__device__ float              g_stg_rw[12];

__constant__ unsigned long long c_w0pk[108];  // (w, w) splat pairs (R9 numerics)
__constant__ unsigned long long c_w1pk[108];
__constant__ unsigned long long c_b0pk[12];
__constant__ unsigned long long c_b1pk[12];
__constant__ float              c_rw1[12];

// ---------------- f32x2 helpers ----------------
__device__ __forceinline__ unsigned long long pack2(unsigned lo, unsigned hi) {
    unsigned long long d;
    asm("mov.b64 %0, {%1, %2};" : "=l"(d) : "r"(lo), "r"(hi));
    return d;
}
__device__ __forceinline__ unsigned long long pack2f(float lo, float hi) {
    return pack2(__float_as_uint(lo), __float_as_uint(hi));
}
__device__ __forceinline__ void unpack2(unsigned long long v, float& lo, float& hi) {
    asm("mov.b64 {%0, %1}, %2;" : "=f"(lo), "=f"(hi) : "l"(v));
}
__device__ __forceinline__ unsigned long long swap2(unsigned long long v) {
    float lo, hi; unpack2(v, lo, hi);
    return pack2f(hi, lo);
}
__device__ __forceinline__ unsigned long long fadd2(unsigned long long a, unsigned long long b) {
    unsigned long long d;
    asm("add.rn.f32x2 %0, %1, %2;" : "=l"(d) : "l"(a), "l"(b));
    return d;
}
__device__ __forceinline__ unsigned long long ffma2(unsigned long long a, unsigned long long b,
                                                    unsigned long long c) {
    unsigned long long d;
    asm("fma.rn.f32x2 %0, %1, %2, %3;" : "=l"(d) : "l"(a), "l"(b), "l"(c));
    return d;
}
// bf16-pair word -> f32x2: lo lane = w<<16, hi lane = w & 0xFFFF0000 (both exact)
__device__ __forceinline__ unsigned long long bfpair(unsigned w) {
    unsigned long long d;
    asm("{\n\t"
        ".reg .b32 lo, hi;\n\t"
        "shl.b32 lo, %1, 16;\n\t"
        "and.b32 hi, %1, 0xFFFF0000;\n\t"
        "mov.b64 %0, {lo, hi};\n\t"
        "}" : "=l"(d) : "r"(w));
    return d;
}
// magic offset: 12582912 = 1.5*2^23 = 0x4B400000. Accumulators kept at M+value
// stay in [2^23, 2^24) where ulp = 1, so every fadd IS a round-to-nearest-int.
#define MAGIC_F 12582912.0f
#define M2RINT 0x4B4000004B400000ull

// ---------------- setup: splat weights into pairs (values unchanged) ----------------
__global__ void setup_weights(const float* __restrict__ s0, const float* __restrict__ s1,
                              const float* __restrict__ b0, const float* __restrict__ b1,
                              const float* __restrict__ rw) {
    int i = threadIdx.x;
    if (i < 108) {
        g_stg_w0[i] = pack2f(s0[i], s0[i]);
        g_stg_w1[i] = pack2f(s1[i], s1[i]);
    }
    if (i < 12) {
        g_stg_b0[i] = pack2f(b0[i], b0[i]);
        g_stg_b1[i] = pack2f(b1[i], b1[i]);
        g_stg_rw[i] = fminf(fmaxf(rw[i], 0.0f), 1.0f);
    }
}

// ---------------- LUT quantization ----------------
__global__ void quant_lut0(const float* __restrict__ src) {
    int i = blockIdx.x * blockDim.x + threadIdx.x;
    if (i < 3 * LUT_N) {
        float q = rintf(src[i] * 127.0f);
        q = fminf(fmaxf(q, -127.0f), 127.0f);
        g_q0[i] = (int8_t)(int)q;
    }
}

// quantize to int value, return top-16 bits of the f32 (== bf16, exact for ints <= 255)
__device__ __forceinline__ unsigned q1bf(float v) {
    float q = rintf(v * 127.0f);
    q = fminf(fmaxf(q, -127.0f), 127.0f);
    return __float_as_uint(q) >> 16;
}

// ---------------- helpers ----------------
// Rotation-r tap position in the 5x5 neighborhood.
// r=0: X[p+u,q+v]; r=1: X[p+v,q-u]; r=2: X[p-u,q-v]; r=3: X[p-v,q+u]
__device__ __forceinline__ constexpr int nb_idx(int R, int u, int w) {
    int dy = (R == 0) ? u : (R == 1) ? w : (R == 2) ? -u : -w;
    int dx = (R == 0) ? w : (R == 1) ? -u : (R == 2) ? -w : u;
    return (2 + dy) * 5 + (2 + dx);
}

#define CSW(fa_, fb_, ta_, tb_)                         \
    { if (fa_ < fb_) { float tf = fa_; fa_ = fb_; fb_ = tf; \
                       int ti = ta_; ta_ = tb_; tb_ = ti; } }

// 4D simplex, scaled form: t = v/16 (exact), f' = frac(t); ws need no /16
__device__ __forceinline__ void simplex(const float v[4], int verts[5], float ws[5]) {
    float ta = v[0] * 0.0625f, tb = v[1] * 0.0625f;
    float tc = v[2] * 0.0625f, td = v[3] * 0.0625f;
    int la = (int)ta, lb = (int)tb, lc = (int)tc, ld = (int)td;
    float f0 = ta - (float)la, f1 = tb - (float)lb;
    float f2 = tc - (float)lc, f3 = td - (float)ld;
    int base = la * 4913 + lb * 289 + lc * 17 + ld;
    int t0 = 4913, t1 = 289, t2 = 17, t3 = 1;
    CSW(f0, f1, t0, t1); CSW(f2, f3, t2, t3);
    CSW(f0, f2, t0, t2); CSW(f1, f3, t1, t3);
    CSW(f1, f2, t1, t2);
    ws[0] = 1.0f - f0;
    ws[1] = f0 - f1;
    ws[2] = f1 - f2;
    ws[3] = f2 - f3;
    ws[4] = f3;
    verts[0] = base;
    verts[1] = verts[0] + t0;
    verts[2] = verts[1] + t1;
    verts[3] = verts[2] + t2;
    verts[4] = verts[3] + t3;
}

// ---------------- merged stage0 + quant_lut1 ----------------
// blockIdx.z == 0: quant1 slice (scheduled first, overlaps stage0 compute).
// blockIdx.z in 1..4: stage0 for batch b = z-1.
__global__ void __launch_bounds__(256, 3) stage0_kernel(const float* __restrict__ x,
                                                        const float* __restrict__ lut1src) {
    if (blockIdx.z == 0) {
        // quant_lut1 -> split bf16 tables. Thread i handles lo-word and hi-word k
        // of vertex vtx (coalesced float2 reads, coalesced u32 writes per table).
        int tid = threadIdx.y * 32 + threadIdx.x;
        int gidx = (blockIdx.y * 16 + blockIdx.x) * 256 + tid;   // 262144 threads
        const int W = 3 * LUT_N * 4;
        const float2* s2 = reinterpret_cast<const float2*>(lut1src);
#pragma unroll
        for (int it = 0; it < 4; it++) {
            int i = gidx + it * 262144;
            if (i < W) {
                int vtx = i >> 2, k = i & 3;
                float2 a = s2[vtx * 8 + k];        // channels 2k, 2k+1
                float2 b = s2[vtx * 8 + 4 + k];    // channels 8+2k, 9+2k
                unsigned wlo = q1bf(a.x) | (q1bf(a.y) << 16);
                unsigned whi = q1bf(b.x) | (q1bf(b.y) << 16);
                reinterpret_cast<unsigned*>(g_q1lo)[vtx * 4 + k] = wlo;
                reinterpret_cast<unsigned*>(g_q1hi)[vtx * 4 + k] = whi;
            }
        }
        return;
    }

    int q = blockIdx.x * 32 + threadIdx.x;
    int p = blockIdx.y * 8 + threadIdx.y;
    int b = blockIdx.z - 1;

    unsigned long long pkA[9], pkB[9];   // (R0,R2) and (R1,R3) packed taps
    {
        const float* img = x + (size_t)b * NN * NN;
        float nb[25];
        int rr[5], cc[5];
#pragma unroll
        for (int i = 0; i < 5; i++) {
            rr[i] = min(max(p - 2 + i, 0), NN - 1);
            cc[i] = min(max(q - 2 + i, 0), NN - 1);
        }
#pragma unroll
        for (int i = 0; i < 5; i++)
#pragma unroll
            for (int j = 0; j < 5; j++)
                nb[i * 5 + j] = 255.0f * __ldg(img + rr[i] * NN + cc[j]);
#pragma unroll
        for (int u = 0; u < 3; u++)
#pragma unroll
            for (int w = 0; w < 3; w++) {
                int iA = nb_idx(0, u, w);
                int iB = nb_idx(1, u, w);
                pkA[u * 3 + w] = pack2f(nb[iA], nb[24 - iA]);
                pkB[u * 3 + w] = pack2f(nb[iB], nb[24 - iB]);
            }
    }

    // magic-domain rintf chain: total_m += dot rounds (total + dot) to int (ulp=1)
    float total_m = MAGIC_F;
#pragma unroll
    for (int s = 0; s < 3; s++) {
        const int8_t* lt = g_q0 + s * LUT_N;

        float v[4][4];
#pragma unroll
        for (int ch = 0; ch < 4; ch++) {
            unsigned long long accA = c_b0pk[s * 4 + ch];
            unsigned long long accB = accA;
#pragma unroll
            for (int t = 0; t < 9; t++) {
                unsigned long long w2 = c_w0pk[s * 36 + ch * 9 + t];
                accA = ffma2(w2, pkA[t], accA);
                accB = ffma2(w2, pkB[t], accB);
            }
            unpack2(accA, v[0][ch], v[2][ch]);
            unpack2(accB, v[1][ch], v[3][ch]);
        }

#pragma unroll
        for (int R = 0; R < 4; R++) {
            int verts[5]; float ws[5];
            simplex(v[R], verts, ws);
            float dot = 0.0f;
#pragma unroll
            for (int t = 0; t < 5; t++) dot += ws[t] * (float)__ldg(lt + verts[t]);
            total_m += dot;   // auto-rint at ulp 1
        }
    }
    float total = total_m - MAGIC_F;
    float o = rintf(fminf(fmaxf(total * (1.0f / 12.0f) + 127.0f, 0.0f), 255.0f));
    g_x1[(size_t)b * NN * NN + p * NN + q] = o;
}

// ---------------- stage 1 ----------------
// fused per-rotation: simplex + two-table bf16 gather + accumulate into
// magic-domain blk2[8]; blk2 += c2 == blk += rint(c) per lane (ulp 1)
template <int R>
__device__ __forceinline__ void proc_rot1(const float v[4],
                                          const uint4* __restrict__ ltlo,
                                          const uint4* __restrict__ lthi,
                                          unsigned long long blk2[8]) {
    int vt[5]; float ws[5];
    simplex(v, vt, ws);

    unsigned long long wt2[5];
#pragma unroll
    for (int t = 0; t < 5; t++) {
        unsigned wtb = __float_as_uint(ws[t]);
        wt2[t] = pack2(wtb, wtb);
    }

    unsigned long long c2[8];
#pragma unroll
    for (int pidx = 0; pidx < 8; pidx++) c2[pidx] = 0ull;

    // phase A: channels 0-7
    {
        uint4 d[5];
#pragma unroll
        for (int t = 0; t < 5; t++) d[t] = __ldg(ltlo + vt[t]);
#pragma unroll
        for (int t = 0; t < 5; t++) {
            c2[0] = ffma2(wt2[t], bfpair(d[t].x), c2[0]);
            c2[1] = ffma2(wt2[t], bfpair(d[t].y), c2[1]);
            c2[2] = ffma2(wt2[t], bfpair(d[t].z), c2[2]);
            c2[3] = ffma2(wt2[t], bfpair(d[t].w), c2[3]);
        }
    }
    // phase B: channels 8-15
    {
        uint4 d[5];
#pragma unroll
        for (int t = 0; t < 5; t++) d[t] = __ldg(lthi + vt[t]);
#pragma unroll
        for (int t = 0; t < 5; t++) {
            c2[4] = ffma2(wt2[t], bfpair(d[t].x), c2[4]);
            c2[5] = ffma2(wt2[t], bfpair(d[t].y), c2[5]);
            c2[6] = ffma2(wt2[t], bfpair(d[t].z), c2[6]);
            c2[7] = ffma2(wt2[t], bfpair(d[t].w), c2[7]);
        }
    }

    if (R == 0) {
#pragma unroll
        for (int bq = 0; bq < 8; bq++)
            blk2[bq] = fadd2(blk2[bq], c2[bq]);
    } else if (R == 2) {
        // k = 15 - (i*4+j): blk pair b <- c pair 7-b, lanes swapped
#pragma unroll
        for (int bq = 0; bq < 8; bq++)
            blk2[bq] = fadd2(blk2[bq], swap2(c2[7 - bq]));
    } else {
        float c[16];
#pragma unroll
        for (int pidx = 0; pidx < 8; pidx++) unpack2(c2[pidx], c[2 * pidx], c[2 * pidx + 1]);
#pragma unroll
        for (int bq = 0; bq < 8; bq++) {
            int i = bq >> 1, j0 = (bq & 1) * 2;
            int k0 = (R == 1) ? ((3 - j0) * 4 + i) : (j0 * 4 + (3 - i));
            int k1 = (R == 1) ? ((3 - j0 - 1) * 4 + i) : ((j0 + 1) * 4 + (3 - i));
            blk2[bq] = fadd2(blk2[bq], pack2f(c[k0], c[k1]));
        }
    }
}

__global__ void __launch_bounds__(256, 2) stage1_kernel(const float* __restrict__ x,
                                                        float* __restrict__ out) {
    int q = blockIdx.x * 32 + threadIdx.x;
    int p = blockIdx.y * 8 + threadIdx.y;
    int b = blockIdx.z;

    // packed neighborhood: lane0 = current image (g_x1), lane1 = prev image (255*x)
    unsigned long long pnb[25];
    {
        const float* img1 = g_x1 + (size_t)b * NN * NN;
        const float* img0 = x + (size_t)b * NN * NN;
        int rr[5], cc[5];
#pragma unroll
        for (int i = 0; i < 5; i++) {
            rr[i] = min(max(p - 2 + i, 0), NN - 1);
            cc[i] = min(max(q - 2 + i, 0), NN - 1);
        }
#pragma unroll
        for (int i = 0; i < 5; i++)
#pragma unroll
            for (int j = 0; j < 5; j++) {
                int off = rr[i] * NN + cc[j];
                pnb[i * 5 + j] = pack2f(__ldg(img1 + off), 255.0f * __ldg(img0 + off));
            }
    }

    unsigned long long blk2[8];
#pragma unroll
    for (int k = 0; k < 8; k++) blk2[k] = M2RINT;   // magic-domain zero

#pragma unroll
    for (int s = 0; s < 3; s++) {
        const uint4* ltlo = g_q1lo + s * LUT_N;
        const uint4* lthi = g_q1hi + s * LUT_N;

        // ---- paired conv (cur, prev share weights), splatted constant pairs ----
        float v[4][4];   // [R][ch], blended
#pragma unroll
        for (int ch = 0; ch < 4; ch++) {
            unsigned long long B2b = c_b1pk[s * 4 + ch];
            float rwc = c_rw1[s * 4 + ch];
#pragma unroll
            for (int R = 0; R < 4; R++) {
                unsigned long long a2 = B2b;
#pragma unroll
                for (int u = 0; u < 3; u++)
#pragma unroll
                    for (int w = 0; w < 3; w++)
                        a2 = ffma2(c_w1pk[s * 36 + ch * 9 + u * 3 + w],
                                   pnb[nb_idx(R, u, w)], a2);
                float vc, vp;
                unpack2(a2, vc, vp);
                v[R][ch] = vc + rwc * (vp - vc);
            }
        }

        proc_rot1<0>(v[0], ltlo, lthi, blk2);
        proc_rot1<1>(v[1], ltlo, lthi, blk2);
        proc_rot1<2>(v[2], ltlo, lthi, blk2);
        proc_rot1<3>(v[3], ltlo, lthi, blk2);
    }

    float blk[16];
#pragma unroll
    for (int k = 0; k < 8; k++) {
        float lo, hi;
        unpack2(blk2[k], lo, hi);
        blk[2 * k] = lo - MAGIC_F;       // exact
        blk[2 * k + 1] = hi - MAGIC_F;
    }

    float* op = out + ((size_t)b << 22) + (size_t)(4 * p) * 2048 + 4 * q;
#pragma unroll
    for (int i = 0; i < 4; i++) {
        float4 o;
        o.x = rintf(fminf(fmaxf(blk[i * 4 + 0] * (1.0f / 3.0f), 0.0f), 255.0f)) * (1.0f / 255.0f);
        o.y = rintf(fminf(fmaxf(blk[i * 4 + 1] * (1.0f / 3.0f), 0.0f), 255.0f)) * (1.0f / 255.0f);
        o.z = rintf(fminf(fmaxf(blk[i * 4 + 2] * (1.0f / 3.0f), 0.0f), 255.0f)) * (1.0f / 255.0f);
        o.w = rintf(fminf(fmaxf(blk[i * 4 + 3] * (1.0f / 3.0f), 0.0f), 255.0f)) * (1.0f / 255.0f);
        *reinterpret_cast<float4*>(op + (size_t)i * 2048) = o;
    }
}

// ---------------- launch ----------------
extern "C" void kernel_launch(void* const* d_in, const int* in_sizes, int n_in,
                              void* d_out, int out_size) {
    const float* x     = (const float*)d_in[0];
    const float* lut0  = (const float*)d_in[1];
    const float* lut1  = (const float*)d_in[2];
    const float* samp0 = (const float*)d_in[3];
    const float* samp1 = (const float*)d_in[4];
    const float* sb0   = (const float*)d_in[5];
    const float* sb1   = (const float*)d_in[6];
    const float* resw  = (const float*)d_in[7];

    setup_weights<<<1, 128>>>(samp0, samp1, sb0, sb1, resw);

    void *pw0, *pw1, *pb0, *pb1, *prw;
    cudaGetSymbolAddress(&pw0, g_stg_w0);
    cudaGetSymbolAddress(&pw1, g_stg_w1);
    cudaGetSymbolAddress(&pb0, g_stg_b0);
    cudaGetSymbolAddress(&pb1, g_stg_b1);
    cudaGetSymbolAddress(&prw, g_stg_rw);
    cudaMemcpyToSymbolAsync(c_w0pk, pw0, 108 * 8, 0, cudaMemcpyDeviceToDevice);
    cudaMemcpyToSymbolAsync(c_w1pk, pw1, 108 * 8, 0, cudaMemcpyDeviceToDevice);
    cudaMemcpyToSymbolAsync(c_b0pk, pb0, 12 * 8, 0, cudaMemcpyDeviceToDevice);
    cudaMemcpyToSymbolAsync(c_b1pk, pb1, 12 * 8, 0, cudaMemcpyDeviceToDevice);
    cudaMemcpyToSymbolAsync(c_rw1,  prw, 12 * 4, 0, cudaMemcpyDeviceToDevice);

    quant_lut0<<<(3 * LUT_N + 255) / 256, 256>>>(lut0);

    dim3 blk0(32, 8, 1);
    dim3 grd0(NN / 32, NN / 8, 5);   // z=0: quant1 slice; z=1..4: stage0 batches
    stage0_kernel<<<grd0, blk0>>>(x, lut1);

    dim3 blk1(32, 8, 1);
    dim3 grd1(NN / 32, NN / 8, 4);
    stage1_kernel<<<grd1, blk1>>>(x, (float*)d_out);
}

// round 17
// speedup vs baseline: 1.2508x; 1.2508x over previous
#include <cuda_runtime.h>
#include <cstdint>

#define NN 512
#define LUT_N 83521            // 17^4
#define NPIX (4 * NN * NN)

// ---------------- device scratch ----------------
__device__ int8_t g_q0[3 * LUT_N];        // stage-0 quantized LUT (int8)
__device__ uint4  g_q1[3 * LUT_N];        // stage-1 LUT (16 ch, biased u8, 16B/row)
__device__ float  g_x1[NPIX];             // stage-0 output image (integers 0..255)

// consolidated constants: one staging struct, ONE memcpy, one __constant__ block
struct ConstBlk {
    unsigned long long w0[108];   // (w, w) splat pairs (R9 numerics)
    unsigned long long w1[108];
    unsigned long long b0[12];
    unsigned long long b1[12];
    float rw[12];
};
__device__ ConstBlk g_stg;
__constant__ ConstBlk c_cb;

// ---------------- f32x2 helpers ----------------
__device__ __forceinline__ unsigned long long pack2(unsigned lo, unsigned hi) {
    unsigned long long d;
    asm("mov.b64 %0, {%1, %2};" : "=l"(d) : "r"(lo), "r"(hi));
    return d;
}
__device__ __forceinline__ unsigned long long pack2f(float lo, float hi) {
    return pack2(__float_as_uint(lo), __float_as_uint(hi));
}
__device__ __forceinline__ void unpack2(unsigned long long v, float& lo, float& hi) {
    asm("mov.b64 {%0, %1}, %2;" : "=f"(lo), "=f"(hi) : "l"(v));
}
__device__ __forceinline__ unsigned long long swap2(unsigned long long v) {
    float lo, hi; unpack2(v, lo, hi);
    return pack2f(hi, lo);
}
__device__ __forceinline__ unsigned long long fadd2(unsigned long long a, unsigned long long b) {
    unsigned long long d;
    asm("add.rn.f32x2 %0, %1, %2;" : "=l"(d) : "l"(a), "l"(b));
    return d;
}
__device__ __forceinline__ unsigned long long fsub2(unsigned long long a, unsigned long long b) {
    unsigned long long d;
    asm("sub.rn.f32x2 %0, %1, %2;" : "=l"(d) : "l"(a), "l"(b));
    return d;
}
__device__ __forceinline__ unsigned long long ffma2(unsigned long long a, unsigned long long b,
                                                    unsigned long long c) {
    unsigned long long d;
    asm("fma.rn.f32x2 %0, %1, %2, %3;" : "=l"(d) : "l"(a), "l"(b), "l"(c));
    return d;
}
// magic offset: 12582912 = 1.5*2^23 = 0x4B400000. Accumulators kept at M+value
// stay in [2^23, 2^24) where ulp = 1, so every fadd IS a round-to-nearest-int.
#define MAGIC_F 12582912.0f
#define M2RINT 0x4B4000004B400000ull

// ---------------- setup: weights splat + quant_lut0 (one kernel) ----------------
// grid: 980 blocks x 256 threads covers 3*LUT_N quant0 elements; block 0 also
// writes the staging struct. stage0 (a LATER kernel) reads g_q0 -> safe.
__global__ void setup_kernel(const float* __restrict__ s0, const float* __restrict__ s1,
                             const float* __restrict__ b0, const float* __restrict__ b1,
                             const float* __restrict__ rw, const float* __restrict__ lut0) {
    int i = blockIdx.x * 256 + threadIdx.x;
    if (i < 3 * LUT_N) {
        float q = rintf(lut0[i] * 127.0f);
        q = fminf(fmaxf(q, -127.0f), 127.0f);
        g_q0[i] = (int8_t)(int)q;
    }
    if (blockIdx.x == 0) {
        int t = threadIdx.x;
        if (t < 108) {
            g_stg.w0[t] = pack2f(s0[t], s0[t]);
            g_stg.w1[t] = pack2f(s1[t], s1[t]);
        }
        if (t < 12) {
            g_stg.b0[t] = pack2f(b0[t], b0[t]);
            g_stg.b1[t] = pack2f(b1[t], b1[t]);
            g_stg.rw[t] = fminf(fmaxf(rw[t], 0.0f), 1.0f);
        }
    }
}

__device__ __forceinline__ unsigned q1_byte(float v) {
    float q = rintf(v * 127.0f);
    q = fminf(fmaxf(q, -127.0f), 127.0f);
    return (unsigned)((int)q + 128);   // biased u8
}

// ---------------- helpers ----------------
// Rotation-r tap position in the 5x5 neighborhood.
// r=0: X[p+u,q+v]; r=1: X[p+v,q-u]; r=2: X[p-u,q-v]; r=3: X[p-v,q+u]
__device__ __forceinline__ constexpr int nb_idx(int R, int u, int w) {
    int dy = (R == 0) ? u : (R == 1) ? w : (R == 2) ? -u : -w;
    int dx = (R == 0) ? w : (R == 1) ? -u : (R == 2) ? -w : u;
    return (2 + dy) * 5 + (2 + dx);
}

#define CSW(fa_, fb_, ta_, tb_)                         \
    { if (fa_ < fb_) { float tf = fa_; fa_ = fb_; fb_ = tf; \
                       int ti = ta_; ta_ = tb_; tb_ = ti; } }

// 4D simplex, scaled form: t = v/16 (exact), f' = frac(t); ws need no /16
__device__ __forceinline__ void simplex(const float v[4], int verts[5], float ws[5]) {
    float ta = v[0] * 0.0625f, tb = v[1] * 0.0625f;
    float tc = v[2] * 0.0625f, td = v[3] * 0.0625f;
    int la = (int)ta, lb = (int)tb, lc = (int)tc, ld = (int)td;
    float f0 = ta - (float)la, f1 = tb - (float)lb;
    float f2 = tc - (float)lc, f3 = td - (float)ld;
    int base = la * 4913 + lb * 289 + lc * 17 + ld;
    int t0 = 4913, t1 = 289, t2 = 17, t3 = 1;
    CSW(f0, f1, t0, t1); CSW(f2, f3, t2, t3);
    CSW(f0, f2, t0, t2); CSW(f1, f3, t1, t3);
    CSW(f1, f2, t1, t2);
    ws[0] = 1.0f - f0;
    ws[1] = f0 - f1;
    ws[2] = f1 - f2;
    ws[3] = f2 - f3;
    ws[4] = f3;
    verts[0] = base;
    verts[1] = verts[0] + t0;
    verts[2] = verts[1] + t1;
    verts[3] = verts[2] + t2;
    verts[4] = verts[3] + t3;
}

// ---------------- merged stage0 + quant_lut1 ----------------
// blockIdx.z == 0: quant1 slice (scheduled first, overlaps stage0 compute).
// blockIdx.z in 1..4: stage0 for batch b = z-1.
__global__ void __launch_bounds__(256, 3) stage0_kernel(const float* __restrict__ x,
                                                        const float* __restrict__ lut1src) {
    if (blockIdx.z == 0) {
        int tid = threadIdx.y * 32 + threadIdx.x;
        int gidx = (blockIdx.y * 16 + blockIdx.x) * 256 + tid;   // 262144 threads
        const int W = 3 * LUT_N * 4;
#pragma unroll
        for (int it = 0; it < 4; it++) {
            int i = gidx + it * 262144;
            if (i < W) {
                float4 f = reinterpret_cast<const float4*>(lut1src)[i];
                unsigned acc = q1_byte(f.x) | (q1_byte(f.y) << 8)
                             | (q1_byte(f.z) << 16) | (q1_byte(f.w) << 24);
                reinterpret_cast<unsigned*>(g_q1)[i] = acc;
            }
        }
        return;
    }

    int q = blockIdx.x * 32 + threadIdx.x;
    int p = blockIdx.y * 8 + threadIdx.y;
    int b = blockIdx.z - 1;

    unsigned long long pkA[9], pkB[9];   // (R0,R2) and (R1,R3) packed taps
    {
        const float* img = x + (size_t)b * NN * NN;
        float nb[25];
        int rr[5], cc[5];
#pragma unroll
        for (int i = 0; i < 5; i++) {
            rr[i] = min(max(p - 2 + i, 0), NN - 1);
            cc[i] = min(max(q - 2 + i, 0), NN - 1);
        }
#pragma unroll
        for (int i = 0; i < 5; i++)
#pragma unroll
            for (int j = 0; j < 5; j++)
                nb[i * 5 + j] = 255.0f * __ldg(img + rr[i] * NN + cc[j]);
#pragma unroll
        for (int u = 0; u < 3; u++)
#pragma unroll
            for (int w = 0; w < 3; w++) {
                int iA = nb_idx(0, u, w);
                int iB = nb_idx(1, u, w);
                pkA[u * 3 + w] = pack2f(nb[iA], nb[24 - iA]);
                pkB[u * 3 + w] = pack2f(nb[iB], nb[24 - iB]);
            }
    }

    // magic-domain rintf chain: total_m += dot rounds (total + dot) to int (ulp=1)
    float total_m = MAGIC_F;
#pragma unroll
    for (int s = 0; s < 3; s++) {
        const int8_t* lt = g_q0 + s * LUT_N;

        float v[4][4];
#pragma unroll
        for (int ch = 0; ch < 4; ch++) {
            unsigned long long accA = c_cb.b0[s * 4 + ch];
            unsigned long long accB = accA;
#pragma unroll
            for (int t = 0; t < 9; t++) {
                unsigned long long w2 = c_cb.w0[s * 36 + ch * 9 + t];
                accA = ffma2(w2, pkA[t], accA);
                accB = ffma2(w2, pkB[t], accB);
            }
            unpack2(accA, v[0][ch], v[2][ch]);
            unpack2(accB, v[1][ch], v[3][ch]);
        }

#pragma unroll
        for (int R = 0; R < 4; R++) {
            int verts[5]; float ws[5];
            simplex(v[R], verts, ws);
            float dot = 0.0f;
#pragma unroll
            for (int t = 0; t < 5; t++) dot += ws[t] * (float)__ldg(lt + verts[t]);
            total_m += dot;   // auto-rint at ulp 1
        }
    }
    float total = total_m - MAGIC_F;
    float o = rintf(fminf(fmaxf(total * (1.0f / 12.0f) + 127.0f, 0.0f), 255.0f));
    g_x1[(size_t)b * NN * NN + p * NN + q] = o;
}

// ---------------- stage 1 ----------------
// fused per-rotation: simplex + gather + diff-from-base accumulate into
// magic-domain blk2[8]; blk2 += c2 == blk += rint(c) per lane (ulp 1).
// c = L0 + sum_{t>=1} ws_t*(L_t - L0); diffs of magic-packed words are exact.
template <int R>
__device__ __forceinline__ void proc_rot1(const float v[4], const uint4* __restrict__ lt,
                                          unsigned long long blk2[8]) {
    int vt[5]; float ws[5];
    simplex(v, vt, ws);

    uint4 d[5];
#pragma unroll
    for (int t = 0; t < 5; t++) d[t] = __ldg(lt + vt[t]);

    unsigned long long wt2[4];
#pragma unroll
    for (int t = 0; t < 4; t++) {
        unsigned wtb = __float_as_uint(ws[t + 1]);
        wt2[t] = pack2(wtb, wtb);
    }
    const unsigned long long B2 = pack2(0xCB000080u, 0xCB000080u);  // (-8388736,-8388736)

    unsigned long long c2[8];
#pragma unroll
    for (int pidx = 0; pidx < 8; pidx++) {
        const int kk = (pidx & 1) * 2;
        unsigned w0 = (pidx < 2) ? d[0].x : (pidx < 4) ? d[0].y : (pidx < 6) ? d[0].z : d[0].w;
        unsigned long long m0 =
            pack2(__byte_perm(w0, 0x4B000000u, 0x7540u + kk),
                  __byte_perm(w0, 0x4B000000u, 0x7541u + kk));
        unsigned long long acc = fadd2(m0, B2);   // exact: L0 per lane
#pragma unroll
        for (int t = 1; t < 5; t++) {
            unsigned wt = (pidx < 2) ? d[t].x : (pidx < 4) ? d[t].y
                        : (pidx < 6) ? d[t].z : d[t].w;
            unsigned long long mt =
                pack2(__byte_perm(wt, 0x4B000000u, 0x7540u + kk),
                      __byte_perm(wt, 0x4B000000u, 0x7541u + kk));
            acc = ffma2(wt2[t - 1], fsub2(mt, m0), acc);   // diff exact (bias cancels)
        }
        c2[pidx] = acc;
    }

    if (R == 0) {
#pragma unroll
        for (int bq = 0; bq < 8; bq++)
            blk2[bq] = fadd2(blk2[bq], c2[bq]);
    } else if (R == 2) {
        // k = 15 - (i*4+j): blk pair b <- c pair 7-b, lanes swapped
#pragma unroll
        for (int bq = 0; bq < 8; bq++)
            blk2[bq] = fadd2(blk2[bq], swap2(c2[7 - bq]));
    } else {
        float c[16];
#pragma unroll
        for (int pidx = 0; pidx < 8; pidx++) unpack2(c2[pidx], c[2 * pidx], c[2 * pidx + 1]);
#pragma unroll
        for (int bq = 0; bq < 8; bq++) {
            int i = bq >> 1, j0 = (bq & 1) * 2;
            int k0 = (R == 1) ? ((3 - j0) * 4 + i) : (j0 * 4 + (3 - i));
            int k1 = (R == 1) ? ((3 - j0 - 1) * 4 + i) : ((j0 + 1) * 4 + (3 - i));
            blk2[bq] = fadd2(blk2[bq], pack2f(c[k0], c[k1]));
        }
    }
}

__global__ void __launch_bounds__(256, 2) stage1_kernel(const float* __restrict__ x,
                                                        float* __restrict__ out) {
    int q = blockIdx.x * 32 + threadIdx.x;
    int p = blockIdx.y * 8 + threadIdx.y;
    int b = blockIdx.z;

    // packed neighborhood: lane0 = current image (g_x1), lane1 = prev image (255*x)
    unsigned long long pnb[25];
    {
        const float* img1 = g_x1 + (size_t)b * NN * NN;
        const float* img0 = x + (size_t)b * NN * NN;
        int rr[5], cc[5];
#pragma unroll
        for (int i = 0; i < 5; i++) {
            rr[i] = min(max(p - 2 + i, 0), NN - 1);
            cc[i] = min(max(q - 2 + i, 0), NN - 1);
        }
#pragma unroll
        for (int i = 0; i < 5; i++)
#pragma unroll
            for (int j = 0; j < 5; j++) {
                int off = rr[i] * NN + cc[j];
                pnb[i * 5 + j] = pack2f(__ldg(img1 + off), 255.0f * __ldg(img0 + off));
            }
    }

    unsigned long long blk2[8];
#pragma unroll
    for (int k = 0; k < 8; k++) blk2[k] = M2RINT;   // magic-domain zero

#pragma unroll
    for (int s = 0; s < 3; s++) {
        const uint4* lt = g_q1 + s * LUT_N;

        // ---- paired conv (cur, prev share weights), splatted constant pairs ----
        float v[4][4];   // [R][ch], blended
#pragma unroll
        for (int ch = 0; ch < 4; ch++) {
            unsigned long long B2b = c_cb.b1[s * 4 + ch];
            float rwc = c_cb.rw[s * 4 + ch];
#pragma unroll
            for (int R = 0; R < 4; R++) {
                unsigned long long a2 = B2b;
#pragma unroll
                for (int u = 0; u < 3; u++)
#pragma unroll
                    for (int w = 0; w < 3; w++)
                        a2 = ffma2(c_cb.w1[s * 36 + ch * 9 + u * 3 + w],
                                   pnb[nb_idx(R, u, w)], a2);
                float vc, vp;
                unpack2(a2, vc, vp);
                v[R][ch] = vc + rwc * (vp - vc);
            }
        }

        proc_rot1<0>(v[0], lt, blk2);
        proc_rot1<1>(v[1], lt, blk2);
        proc_rot1<2>(v[2], lt, blk2);
        proc_rot1<3>(v[3], lt, blk2);
    }

    float blk[16];
#pragma unroll
    for (int k = 0; k < 8; k++) {
        float lo, hi;
        unpack2(blk2[k], lo, hi);
        blk[2 * k] = lo - MAGIC_F;       // exact
        blk[2 * k + 1] = hi - MAGIC_F;
    }

    float* op = out + ((size_t)b << 22) + (size_t)(4 * p) * 2048 + 4 * q;
#pragma unroll
    for (int i = 0; i < 4; i++) {
        float4 o;
        o.x = rintf(fminf(fmaxf(blk[i * 4 + 0] * (1.0f / 3.0f), 0.0f), 255.0f)) * (1.0f / 255.0f);
        o.y = rintf(fminf(fmaxf(blk[i * 4 + 1] * (1.0f / 3.0f), 0.0f), 255.0f)) * (1.0f / 255.0f);
        o.z = rintf(fminf(fmaxf(blk[i * 4 + 2] * (1.0f / 3.0f), 0.0f), 255.0f)) * (1.0f / 255.0f);
        o.w = rintf(fminf(fmaxf(blk[i * 4 + 3] * (1.0f / 3.0f), 0.0f), 255.0f)) * (1.0f / 255.0f);
        *reinterpret_cast<float4*>(op + (size_t)i * 2048) = o;
    }
}

// ---------------- launch ----------------
extern "C" void kernel_launch(void* const* d_in, const int* in_sizes, int n_in,
                              void* d_out, int out_size) {
    const float* x     = (const float*)d_in[0];
    const float* lut0  = (const float*)d_in[1];
    const float* lut1  = (const float*)d_in[2];
    const float* samp0 = (const float*)d_in[3];
    const float* samp1 = (const float*)d_in[4];
    const float* sb0   = (const float*)d_in[5];
    const float* sb1   = (const float*)d_in[6];
    const float* resw  = (const float*)d_in[7];

    // setup: weight splats + quant0 in one kernel
    setup_kernel<<<(3 * LUT_N + 255) / 256, 256>>>(samp0, samp1, sb0, sb1, resw, lut0);

    // one consolidated constant upload
    void* pstg;
    cudaGetSymbolAddress(&pstg, g_stg);
    cudaMemcpyToSymbolAsync(c_cb, pstg, sizeof(ConstBlk), 0, cudaMemcpyDeviceToDevice);

    dim3 blk0(32, 8, 1);
    dim3 grd0(NN / 32, NN / 8, 5);   // z=0: quant1 slice; z=1..4: stage0 batches
    stage0_kernel<<<grd0, blk0>>>(x, lut1);

    dim3 blk1(32, 8, 1);
    dim3 grd1(NN / 32, NN / 8, 4);
    stage1_kernel<<<grd1, blk1>>>(x, (float*)d_out);
}